// round 8
// baseline (speedup 1.0000x reference)
#include <cuda_runtime.h>
#include <cstdint>

#define SLATE   5
#define DDIM    20
#define KSEL    100
#define NBINS   2048
#define CAP     131072
#define SMAX    131072
#define SH_CAND 12288
#define SV_CAP  512
#define STGT    128        // sample-count guarantee target (>= KSEL)
#define STILE   1024       // docs per score tile (80 KB per stage)
#define SBYTES  (STILE * 80)

// -------- device scratch (allocation-free module globals) --------
__device__ float              g_proto[128];
__device__ float              g_pn2[8];
__device__ unsigned           g_hist[SLATE * NBINS];
__device__ unsigned           g_skey[(size_t)SLATE * SMAX];   // sample keys
__device__ unsigned           g_thresh[8];                    // exclusive key limit
__device__ unsigned           g_candCount[8];
__device__ unsigned long long g_cand[(size_t)SLATE * CAP];
__device__ unsigned           g_done;

__device__ __forceinline__ float leaky(float x) { return x > 0.0f ? x : 0.01f * x; }

__device__ __forceinline__ unsigned smem_u32(const void* p) {
    return (unsigned)__cvta_generic_to_shared(p);
}

// ---- TMA 1D bulk + mbarrier helpers ----
__device__ __forceinline__ void mbar_init(unsigned mb, unsigned cnt) {
    asm volatile("mbarrier.init.shared.b64 [%0], %1;" :: "r"(mb), "r"(cnt) : "memory");
}
__device__ __forceinline__ void mbar_expect_tx(unsigned mb, unsigned bytes) {
    asm volatile("mbarrier.arrive.expect_tx.shared.b64 _, [%0], %1;"
                 :: "r"(mb), "r"(bytes) : "memory");
}
__device__ __forceinline__ void bulk_g2s(unsigned sdst, const void* gsrc,
                                         unsigned bytes, unsigned mb) {
    asm volatile(
        "cp.async.bulk.shared::cta.global.mbarrier::complete_tx::bytes "
        "[%0], [%1], %2, [%3];"
        :: "r"(sdst), "l"(gsrc), "r"(bytes), "r"(mb) : "memory");
}
__device__ __forceinline__ void mbar_wait(unsigned mb, unsigned phase) {
    unsigned done;
    do {
        asm volatile(
            "{\n\t.reg .pred p;\n\t"
            "mbarrier.try_wait.parity.acquire.cta.shared::cta.b64 p, [%1], %2, 0x989680;\n\t"
            "selp.b32 %0, 1, 0, p;\n\t}"
            : "=r"(done) : "r"(mb), "r"(phase) : "memory");
    } while (!done);
}

// ---- scalar math: sample AND score use identical sequences (bit-identical keys)
__device__ __forceinline__ void unpack20(const float4* d5, float* vv) {
    #pragma unroll
    for (int q = 0; q < 5; q++) {
        float4 v = d5[q];
        vv[4*q+0] = v.x; vv[4*q+1] = v.y; vv[4*q+2] = v.z; vv[4*q+3] = v.w;
    }
}
__device__ __forceinline__ float norm20(const float* vv) {
    float c = 0.0f;
    #pragma unroll
    for (int k = 0; k < DDIM; k++) c = fmaf(vv[k], vv[k], c);
    return c;
}
__device__ __forceinline__ float dot20v(const float4* p, const float* vv) {
    float d = 0.0f;
    #pragma unroll
    for (int q = 0; q < 5; q++) {
        float4 w = p[q];
        d = fmaf(w.x, vv[4*q+0], d); d = fmaf(w.y, vv[4*q+1], d);
        d = fmaf(w.z, vv[4*q+2], d); d = fmaf(w.w, vv[4*q+3], d);
    }
    return d;
}
__device__ __forceinline__ unsigned key20(float cn2, float dot, float pn) {
    float d2 = fmaf(-2.0f, dot, cn2) + pn;
    d2 = fmaxf(d2, 0.0f);               // positive floats: raw bits monotone
    return __float_as_uint(d2);
}

// ---- block-wide "first bin with inclusive cum >= r" over NB bins ----
template<int NB, int BD>
__device__ void find_bin(const unsigned* hist, unsigned r, unsigned* warpsum,
                         unsigned* s_res, unsigned* s_prefix)
{
    const int tid = threadIdx.x;
    constexpr int PB = NB / BD;
    unsigned local[PB];
    unsigned v = 0;
    #pragma unroll
    for (int p = 0; p < PB; p++) { local[p] = hist[tid * PB + p]; v += local[p]; }

    unsigned inc = v;
    #pragma unroll
    for (int d = 1; d < 32; d <<= 1) {
        unsigned t = __shfl_up_sync(0xFFFFFFFFu, inc, d);
        if ((tid & 31) >= d) inc += t;
    }
    if ((tid & 31) == 31) warpsum[tid >> 5] = inc;
    if (tid == 0) *s_res = 0xFFFFFFFFu;
    __syncthreads();

    if (tid < 32) {
        constexpr int NW = BD / 32;
        unsigned w = (tid < NW) ? warpsum[tid] : 0u;
        #pragma unroll
        for (int d = 1; d < 32; d <<= 1) {
            unsigned t = __shfl_up_sync(0xFFFFFFFFu, w, d);
            if (tid >= d) w += t;
        }
        warpsum[tid] = w;
    }
    __syncthreads();

    unsigned base   = (tid >= 32) ? warpsum[(tid >> 5) - 1] : 0u;
    unsigned before = base + inc - v;
    unsigned run = before;
    unsigned myBin = 0xFFFFFFFFu;
    #pragma unroll
    for (int p = 0; p < PB; p++) {
        run += local[p];
        if (myBin == 0xFFFFFFFFu && run >= r) myBin = (unsigned)(tid * PB + p);
    }
    if (myBin != 0xFFFFFFFFu) atomicMin(s_res, myBin);
    __syncthreads();

    unsigned winner = *s_res;
    if (winner != 0xFFFFFFFFu && winner / PB == (unsigned)tid) {
        unsigned pf = before;
        for (unsigned p = 0; p < winner % PB; p++) pf += local[p];
        *s_prefix = pf;
    }
    __syncthreads();
}

// -------- kernel 1: MLP (o-vectorized float4 GEMVs) + zero scratch --------
__global__ __launch_bounds__(1024) void mlp_kernel(
    const float* __restrict__ x_in,
    const float* __restrict__ W0, const float* __restrict__ b0,
    const float* __restrict__ W1, const float* __restrict__ b1,
    const float* __restrict__ W2, const float* __restrict__ b2)
{
    __shared__ float x[DDIM];
    __shared__ float h0[256];
    __shared__ float h1[512];
    __shared__ float p2[8 * 512];
    __shared__ float p3[32 * 100];
    __shared__ float pr[100];
    int tid = threadIdx.x;

    for (int i = tid; i < SLATE * NBINS; i += 1024) g_hist[i] = 0;
    if (tid < 8) g_candCount[tid] = 0;

    if (tid < DDIM) x[tid] = x_in[tid];
    __syncthreads();

    if (tid < 256) {
        float acc = b0[tid];
        #pragma unroll
        for (int k = 0; k < DDIM; k++) acc = fmaf(x[k], W0[k * 256 + tid], acc);
        h0[tid] = leaky(acc);
    }
    __syncthreads();

    {   // layer 2: 512 outputs; float4 along o, k split 8 ways
        int o4 = (tid & 127);
        int c  = tid >> 7;
        const float4* W1v = (const float4*)W1;
        float4 acc = make_float4(0.f, 0.f, 0.f, 0.f);
        int k0 = c * 32;
        #pragma unroll 8
        for (int k = k0; k < k0 + 32; k++) {
            float h = h0[k];
            float4 w = W1v[k * 128 + o4];
            acc.x = fmaf(h, w.x, acc.x); acc.y = fmaf(h, w.y, acc.y);
            acc.z = fmaf(h, w.z, acc.z); acc.w = fmaf(h, w.w, acc.w);
        }
        ((float4*)(p2 + c * 512))[o4] = acc;
    }
    __syncthreads();
    if (tid < 512) {
        float s = b1[tid];
        #pragma unroll
        for (int c = 0; c < 8; c++) s += p2[c * 512 + tid];
        h1[tid] = leaky(s);
    }
    __syncthreads();

    {   // layer 3: 100 outputs; float4 along o, k split 32 ways
        int t = tid & 31;
        int c = tid >> 5;
        if (t < 25) {
            const float4* W2v = (const float4*)W2;
            float4 acc = make_float4(0.f, 0.f, 0.f, 0.f);
            int k0 = c * 16;
            #pragma unroll 8
            for (int k = k0; k < k0 + 16; k++) {
                float h = h1[k];
                float4 w = W2v[k * 25 + t];
                acc.x = fmaf(h, w.x, acc.x); acc.y = fmaf(h, w.y, acc.y);
                acc.z = fmaf(h, w.z, acc.z); acc.w = fmaf(h, w.w, acc.w);
            }
            p3[c * 100 + 4 * t + 0] = acc.x;
            p3[c * 100 + 4 * t + 1] = acc.y;
            p3[c * 100 + 4 * t + 2] = acc.z;
            p3[c * 100 + 4 * t + 3] = acc.w;
        }
    }
    __syncthreads();
    if (tid < 100) {
        float s = b2[tid];
        #pragma unroll
        for (int c = 0; c < 32; c++) s += p3[c * 100 + tid];
        float v = leaky(s);
        pr[tid] = v;
        g_proto[tid] = v;
    }
    __syncthreads();
    if (tid < SLATE) {
        float s = 0.0f;
        #pragma unroll
        for (int d = 0; d < DDIM; d++) { float v = pr[tid * DDIM + d]; s = fmaf(v, v, s); }
        g_pn2[tid] = s;
    }
}

// -------- kernel 2: sample keys + coarse hist; LAST BLOCK refines thresholds --
__global__ __launch_bounds__(512) void sample_kernel(const float* __restrict__ docs,
                                                     int N, int S)
{
    __shared__ unsigned shist[SLATE * NBINS];   // 40 KB
    __shared__ float    sp[100];
    __shared__ float    spn[SLATE];
    __shared__ unsigned swarp[32];
    __shared__ unsigned sres, spre, slast;
    int tid = threadIdx.x;

    for (int t = tid; t < SLATE * NBINS; t += 512) shist[t] = 0;
    if (tid < 100) sp[tid] = g_proto[tid];
    if (tid < SLATE) spn[tid] = g_pn2[tid];
    __syncthreads();

    const float4* d4 = (const float4*)docs;
    for (int s = blockIdx.x * blockDim.x + tid; s < S; s += gridDim.x * blockDim.x) {
        int i = ((s >> 8) << 13) + (s & 255);   // chunk c -> docs [8192c, 8192c+256)
        if (i >= N) {
            #pragma unroll
            for (int j = 0; j < SLATE; j++)
                g_skey[(size_t)j * SMAX + s] = 0xFFFFFFFFu;   // sentinel
            continue;
        }
        float4 dv[5];
        size_t base = (size_t)i * 5;
        #pragma unroll
        for (int q = 0; q < 5; q++) dv[q] = d4[base + q];
        float vv[20];
        unpack20(dv, vv);
        float cn2 = norm20(vv);
        #pragma unroll
        for (int j = 0; j < SLATE; j++) {
            float dot = dot20v((const float4*)&sp[j * DDIM], vv);
            unsigned key = key20(cn2, dot, spn[j]);
            g_skey[(size_t)j * SMAX + s] = key;
            unsigned hidx = j * NBINS + (key >> 21);
            unsigned am = __activemask();
            unsigned m  = __match_any_sync(am, hidx);
            if ((int)(threadIdx.x & 31) == (__ffs(m) - 1))
                atomicAdd(&shist[hidx], (unsigned)__popc(m));
        }
    }
    __syncthreads();
    for (int t = tid; t < SLATE * NBINS; t += 512) {
        unsigned c = shist[t];
        if (c) atomicAdd(&g_hist[t], c);
    }

    // ---- last-block epilogue: per-row threshold, refined to 2^10 keys ----
    __threadfence();
    if (tid == 0) slast = (atomicAdd(&g_done, 1u) == gridDim.x - 1) ? 1u : 0u;
    __syncthreads();
    if (!slast) return;
    __threadfence();

    for (int r = 0; r < SLATE; r++) {
        for (int i = tid; i < NBINS; i += 512)
            shist[i] = __ldcg(&g_hist[r * NBINS + i]);
        __syncthreads();
        find_bin<NBINS, 512>(shist, STGT, swarp, &sres, &spre);
        unsigned bA = sres, pfA = spre;
        __syncthreads();
        if (bA == 0xFFFFFFFFu) {
            if (tid == 0) g_thresh[r] = 0xFFFFFFFFu;
            __syncthreads();
            continue;
        }
        unsigned rB = STGT - pfA;
        for (int i = tid; i < NBINS; i += 512) shist[i] = 0;
        __syncthreads();
        for (int s = tid; s < S; s += 512) {
            unsigned k = __ldcg(&g_skey[(size_t)r * SMAX + s]);
            if ((k >> 21) == bA) atomicAdd(&shist[(k >> 10) & 0x7FFu], 1u);
        }
        __syncthreads();
        find_bin<NBINS, 512>(shist, rB, swarp, &sres, &spre);
        if (tid == 0) {
            unsigned long long T =
                ((((unsigned long long)bA << 11) | sres) + 1ull) << 10;
            g_thresh[r] = (T > 0xFFFFFFFFull) ? 0xFFFFFFFFu : (unsigned)T;
        }
        __syncthreads();
    }
    if (tid == 0) g_done = 0;   // reset for graph replay
}

// -------- kernel 3: fused score+collect, TMA-bulk double-buffered ----------
// One 1024-thread block per SM; 2 stages x 80 KB. A single cp.async.bulk per
// tile (issued by thread 0) delivers 80 KB straight to smem via the TMA path —
// no per-warp scoreboards, no L1tex wavefront queue. mbarrier parity tracks
// stage completion. Scalar FFMA chains bit-identical to the sample path.
__global__ __launch_bounds__(1024, 1) void score_kernel(const float* __restrict__ docs, int N)
{
    extern __shared__ __align__(16) float sd[];        // 2 * STILE * 20 floats
    __shared__ __align__(16) float sp[100];
    __shared__ float    spn[SLATE];
    __shared__ unsigned sT[SLATE];
    __shared__ __align__(8) unsigned long long mbar[2];
    int tid = threadIdx.x;

    if (tid < 100) sp[tid] = g_proto[tid];
    if (tid < SLATE) { spn[tid] = g_pn2[tid]; sT[tid] = g_thresh[tid]; }
    if (tid == 0) {
        mbar_init(smem_u32(&mbar[0]), 1);
        mbar_init(smem_u32(&mbar[1]), 1);
        asm volatile("fence.proxy.async.shared::cta;" ::: "memory");
    }
    __syncthreads();

    int nTiles = (N + STILE - 1) / STILE;
    int grid   = gridDim.x;
    int t0     = blockIdx.x;
    if (t0 >= nTiles) return;

    const char* gbase = (const char*)docs;
    unsigned sbase = smem_u32(sd);
    const int lane = tid & 31;

    // prologue: issue tiles t0 (stage 0) and t0+grid (stage 1)
    if (tid == 0) {
        {
            int nd = N - t0 * STILE; if (nd > STILE) nd = STILE;
            unsigned bytes = (unsigned)nd * 80u;
            unsigned mb = smem_u32(&mbar[0]);
            mbar_expect_tx(mb, bytes);
            bulk_g2s(sbase, gbase + (size_t)t0 * SBYTES, bytes, mb);
        }
        int t1 = t0 + grid;
        if (t1 < nTiles) {
            int nd = N - t1 * STILE; if (nd > STILE) nd = STILE;
            unsigned bytes = (unsigned)nd * 80u;
            unsigned mb = smem_u32(&mbar[1]);
            mbar_expect_tx(mb, bytes);
            bulk_g2s(sbase + SBYTES, gbase + (size_t)t1 * SBYTES, bytes, mb);
        }
    }

    for (int li = 0;; li++) {
        int tile = t0 + li * grid;
        if (tile >= nTiles) break;
        int st = li & 1;
        unsigned ph = (unsigned)(li >> 1) & 1u;
        mbar_wait(smem_u32(&mbar[st]), ph);

        const float* buf = sd + st * (STILE * DDIM);
        int i = tile * STILE + tid;
        bool ok = i < N;

        float vv[20];
        unpack20((const float4*)(buf + (size_t)tid * DDIM), vv);
        float cn2 = norm20(vv);

        #pragma unroll
        for (int j = 0; j < SLATE; j++) {
            float dot = dot20v((const float4*)&sp[j * DDIM], vv);
            unsigned key = key20(cn2, dot, spn[j]);
            bool hit = ok && (key < sT[j]);
            unsigned am = __activemask();
            unsigned m  = __ballot_sync(am, hit);
            if (m) {
                int ldr = __ffs(m) - 1;
                unsigned bpos = 0;
                if (lane == ldr) bpos = atomicAdd(&g_candCount[j], (unsigned)__popc(m));
                bpos = __shfl_sync(am, bpos, ldr);
                if (hit) {
                    unsigned pos = bpos + (unsigned)__popc(m & ((1u << lane) - 1u));
                    if (pos < CAP)
                        g_cand[(size_t)j * CAP + pos] =
                            ((unsigned long long)key << 32) | (unsigned)i;
                }
            }
        }
        __syncthreads();                 // whole block done with stage st

        int tn = tile + 2 * grid;        // refill freed stage
        if (tn < nTiles && tid == 0) {
            int nd = N - tn * STILE; if (nd > STILE) nd = STILE;
            unsigned bytes = (unsigned)nd * 80u;
            unsigned mb = smem_u32(&mbar[st]);
            mbar_expect_tx(mb, bytes);
            bulk_g2s(sbase + st * SBYTES, gbase + (size_t)tn * SBYTES, bytes, mb);
        }
    }
}

// -------- kernel 4: radix select of exact 100th + rank survivors + gather ----
__global__ __launch_bounds__(1024) void select_kernel(
    const float* __restrict__ docs, float* __restrict__ out, int out_size)
{
    extern __shared__ unsigned long long sc[];
    __shared__ unsigned           hist[NBINS];
    __shared__ unsigned           swarp[32];
    __shared__ unsigned           sres, spre;
    __shared__ unsigned long long sv[SV_CAP];
    __shared__ unsigned           svCount;

    int j   = blockIdx.x;
    int tid = threadIdx.x;
    size_t cbase = (size_t)j * CAP;
    int n = (int)min(g_candCount[j], (unsigned)CAP);
    int nsh = n < SH_CAND ? n : SH_CAND;

    if (tid == 0) svCount = 0;
    for (int t = tid; t < nsh; t += 1024) sc[t] = g_cand[cbase + t];
    __syncthreads();

    // pass A: bits 31..21
    for (int i = tid; i < NBINS; i += 1024) hist[i] = 0;
    __syncthreads();
    for (int t = tid; t < n; t += 1024) {
        unsigned k = (unsigned)(((t < nsh) ? sc[t] : g_cand[cbase + t]) >> 32);
        unsigned b = k >> 21;
        unsigned am = __activemask();
        unsigned m  = __match_any_sync(am, b);
        if ((int)(tid & 31) == (__ffs(m) - 1)) atomicAdd(&hist[b], (unsigned)__popc(m));
    }
    __syncthreads();
    find_bin<NBINS, 1024>(hist, KSEL, swarp, &sres, &spre);
    unsigned bA = sres;
    unsigned rB = KSEL - spre;
    __syncthreads();

    // pass B: bits 20..10 within bA
    for (int i = tid; i < NBINS; i += 1024) hist[i] = 0;
    __syncthreads();
    for (int t = tid; t < n; t += 1024) {
        unsigned k = (unsigned)(((t < nsh) ? sc[t] : g_cand[cbase + t]) >> 32);
        if ((k >> 21) == bA) atomicAdd(&hist[(k >> 10) & 0x7FFu], 1u);
    }
    __syncthreads();
    find_bin<NBINS, 1024>(hist, rB, swarp, &sres, &spre);
    unsigned bB = sres;
    unsigned rC = rB - spre;
    unsigned hi21 = (bA << 11) | bB;
    __syncthreads();

    // pass C: bits 9..0 within (bA,bB)
    if (tid < 1024) hist[tid] = 0;
    __syncthreads();
    for (int t = tid; t < n; t += 1024) {
        unsigned k = (unsigned)(((t < nsh) ? sc[t] : g_cand[cbase + t]) >> 32);
        if ((k >> 10) == hi21) atomicAdd(&hist[k & 0x3FFu], 1u);
    }
    __syncthreads();
    find_bin<1024, 1024>(hist, rC, swarp, &sres, &spre);
    unsigned Kstar = (hi21 << 10) | sres;
    __syncthreads();

    // survivors: key <= Kstar (ties resolved by packed 64-bit rank)
    for (int t = tid; t < n; t += 1024) {
        unsigned long long pk = (t < nsh) ? sc[t] : g_cand[cbase + t];
        if ((unsigned)(pk >> 32) <= Kstar) {
            unsigned pos = atomicAdd(&svCount, 1u);
            if (pos < SV_CAP) sv[pos] = pk;
        }
    }
    __syncthreads();

    int S = (int)min(svCount, (unsigned)SV_CAP);
    for (int t = tid; t < S; t += 1024) {
        unsigned long long my = sv[t];
        int rank = 0;
        for (int s = 0; s < S; s++) rank += (sv[s] < my);
        if (rank < KSEL) {
            unsigned di = (unsigned)(my & 0xFFFFFFFFu);
            int orow = j * KSEL + rank;
            if (out_size >= SLATE * KSEL * DDIM) {
                const float4* s4 = (const float4*)(docs + (size_t)di * DDIM);
                float4* o4 = (float4*)(out + (size_t)orow * DDIM);
                #pragma unroll
                for (int q = 0; q < 5; q++) o4[q] = s4[q];
                if (out_size >= SLATE * KSEL * DDIM + SLATE * KSEL)
                    out[SLATE * KSEL * DDIM + orow] = (float)di;
            } else {
                out[orow] = (float)di;
            }
        }
    }
}

extern "C" void kernel_launch(void* const* d_in, const int* in_sizes, int n_in,
                              void* d_out, int out_size)
{
    const float* state = (const float*)d_in[0];
    const float* docs  = (const float*)d_in[1];
    const float* W0    = (const float*)d_in[2];
    const float* b0    = (const float*)d_in[3];
    const float* W1    = (const float*)d_in[4];
    const float* b1    = (const float*)d_in[5];
    const float* W2    = (const float*)d_in[6];
    const float* b2    = (const float*)d_in[7];
    float* out = (float*)d_out;

    int N = in_sizes[1] / DDIM;
    int S = N >> 5;               // 1/32 sample
    if (S < 1) S = N;
    if (S > SMAX) S = SMAX;

    static int inited = 0;
    if (!inited) {
        cudaFuncSetAttribute(score_kernel,
            cudaFuncAttributeMaxDynamicSharedMemorySize, 2 * SBYTES);
        cudaFuncSetAttribute(select_kernel,
            cudaFuncAttributeMaxDynamicSharedMemorySize, SH_CAND * sizeof(unsigned long long));
        inited = 1;
    }

    int nTiles = (N + STILE - 1) / STILE;
    int sblocks = nTiles < 148 ? nTiles : 148;   // 1 block/SM (smem-bound)
    if (sblocks < 1) sblocks = 1;

    mlp_kernel<<<1, 1024>>>(state, W0, b0, W1, b1, W2, b2);
    sample_kernel<<<128, 512>>>(docs, N, S);
    score_kernel<<<sblocks, 1024, 2 * SBYTES>>>(docs, N);
    select_kernel<<<SLATE, 1024, SH_CAND * sizeof(unsigned long long)>>>(docs, out, out_size);
}

// round 9
// speedup vs baseline: 1.1655x; 1.1655x over previous
#include <cuda_runtime.h>
#include <cstdint>

#define SLATE   5
#define DDIM    20
#define KSEL    100
#define NBINS   2048
#define CAP     131072
#define SMAX    131072
#define SH_CAND 12288
#define SV_CAP  512
#define STGT    128        // sample-count guarantee target (>= KSEL)

// -------- device scratch (allocation-free module globals) --------
__device__ float              g_h1[512];
__device__ float              g_proto[128];
__device__ float              g_pn2[8];
__device__ unsigned           g_hist[SLATE * NBINS];
__device__ unsigned           g_skey[(size_t)SLATE * SMAX];   // sample keys
__device__ unsigned           g_thresh[8];                    // exclusive key limit
__device__ unsigned           g_candCount[8];
__device__ unsigned long long g_cand[(size_t)SLATE * CAP];
__device__ unsigned           g_done;    // sample ticket
__device__ unsigned           g_doneB;   // mlpB ticket

__device__ __forceinline__ float leaky(float x) { return x > 0.0f ? x : 0.01f * x; }

// ---- scalar math: sample AND score use identical sequences (bit-identical keys)
__device__ __forceinline__ void unpack20(const float4* d5, float* vv) {
    #pragma unroll
    for (int q = 0; q < 5; q++) {
        float4 v = d5[q];
        vv[4*q+0] = v.x; vv[4*q+1] = v.y; vv[4*q+2] = v.z; vv[4*q+3] = v.w;
    }
}
__device__ __forceinline__ float norm20(const float* vv) {
    float c = 0.0f;
    #pragma unroll
    for (int k = 0; k < DDIM; k++) c = fmaf(vv[k], vv[k], c);
    return c;
}
__device__ __forceinline__ float dot20v(const float4* p, const float* vv) {
    float d = 0.0f;
    #pragma unroll
    for (int q = 0; q < 5; q++) {
        float4 w = p[q];
        d = fmaf(w.x, vv[4*q+0], d); d = fmaf(w.y, vv[4*q+1], d);
        d = fmaf(w.z, vv[4*q+2], d); d = fmaf(w.w, vv[4*q+3], d);
    }
    return d;
}
__device__ __forceinline__ unsigned key20(float cn2, float dot, float pn) {
    float d2 = fmaf(-2.0f, dot, cn2) + pn;
    d2 = fmaxf(d2, 0.0f);               // positive floats: raw bits monotone
    return __float_as_uint(d2);
}

// ---- block-wide "first bin with inclusive cum >= r" over NB bins ----
template<int NB, int BD>
__device__ void find_bin(const unsigned* hist, unsigned r, unsigned* warpsum,
                         unsigned* s_res, unsigned* s_prefix)
{
    const int tid = threadIdx.x;
    constexpr int PB = NB / BD;
    unsigned local[PB];
    unsigned v = 0;
    #pragma unroll
    for (int p = 0; p < PB; p++) { local[p] = hist[tid * PB + p]; v += local[p]; }

    unsigned inc = v;
    #pragma unroll
    for (int d = 1; d < 32; d <<= 1) {
        unsigned t = __shfl_up_sync(0xFFFFFFFFu, inc, d);
        if ((tid & 31) >= d) inc += t;
    }
    if ((tid & 31) == 31) warpsum[tid >> 5] = inc;
    if (tid == 0) *s_res = 0xFFFFFFFFu;
    __syncthreads();

    if (tid < 32) {
        constexpr int NW = BD / 32;
        unsigned w = (tid < NW) ? warpsum[tid] : 0u;
        #pragma unroll
        for (int d = 1; d < 32; d <<= 1) {
            unsigned t = __shfl_up_sync(0xFFFFFFFFu, w, d);
            if (tid >= d) w += t;
        }
        warpsum[tid] = w;
    }
    __syncthreads();

    unsigned base   = (tid >= 32) ? warpsum[(tid >> 5) - 1] : 0u;
    unsigned before = base + inc - v;
    unsigned run = before;
    unsigned myBin = 0xFFFFFFFFu;
    #pragma unroll
    for (int p = 0; p < PB; p++) {
        run += local[p];
        if (myBin == 0xFFFFFFFFu && run >= r) myBin = (unsigned)(tid * PB + p);
    }
    if (myBin != 0xFFFFFFFFu) atomicMin(s_res, myBin);
    __syncthreads();

    unsigned winner = *s_res;
    if (winner != 0xFFFFFFFFu && winner / PB == (unsigned)tid) {
        unsigned pf = before;
        for (unsigned p = 0; p < winner % PB; p++) pf += local[p];
        *s_prefix = pf;
    }
    __syncthreads();
}

// -------- kernel 1a: layers 0+1 (8 blocks, sliced layer-2 outputs) --------
__global__ __launch_bounds__(256) void mlpA_kernel(
    const float* __restrict__ x_in,
    const float* __restrict__ W0, const float* __restrict__ b0,
    const float* __restrict__ W1, const float* __restrict__ b1)
{
    __shared__ float x[DDIM];
    __shared__ float h0[256];
    __shared__ float part[256];
    int tid = threadIdx.x, b = blockIdx.x;

    // distributed scratch zero (8 blocks x 256 threads cover SLATE*NBINS)
    {
        int gt = b * 256 + tid;
        for (int i = gt; i < SLATE * NBINS; i += 8 * 256) g_hist[i] = 0;
        if (b == 0 && tid < 8) g_candCount[tid] = 0;
    }

    if (tid < DDIM) x[tid] = x_in[tid];
    __syncthreads();

    {   // layer 1: 256 outputs, one per thread, coalesced over W0 columns
        float acc = b0[tid];
        #pragma unroll
        for (int k = 0; k < DDIM; k++) acc = fmaf(x[k], W0[k * 256 + tid], acc);
        h0[tid] = leaky(acc);
    }
    __syncthreads();

    {   // layer 2 slice: outputs [64b, 64b+64); k split 4 ways
        int oo = tid & 63;       // local output
        int c  = tid >> 6;       // 0..3 k-chunk of 64
        float acc = 0.0f;
        int k0 = c * 64;
        #pragma unroll 8
        for (int k = k0; k < k0 + 64; k++)
            acc = fmaf(h0[k], W1[k * 512 + 64 * b + oo], acc);
        part[tid] = acc;
    }
    __syncthreads();
    if (tid < 64) {
        float s = b1[64 * b + tid] + part[tid] + part[64 + tid]
                + part[128 + tid] + part[192 + tid];   // fixed order
        g_h1[64 * b + tid] = leaky(s);
    }
}

// -------- kernel 1b: layer 3 (4 blocks, 25 outputs each) + pn2 ticket ------
__global__ __launch_bounds__(256) void mlpB_kernel(
    const float* __restrict__ W2, const float* __restrict__ b2)
{
    __shared__ float h1s[512];
    __shared__ float part[256];
    __shared__ unsigned slast;
    int tid = threadIdx.x, b = blockIdx.x;

    if (tid < 256) { h1s[tid] = g_h1[tid]; h1s[256 + tid] = g_h1[256 + tid]; }
    __syncthreads();

    {   // outputs [25b, 25b+25); k split 8 ways
        int oo = tid & 31;       // local output (<25 active)
        int c  = tid >> 5;       // 0..7 k-chunk of 64
        float acc = 0.0f;
        if (oo < 25) {
            int k0 = c * 64;
            #pragma unroll 8
            for (int k = k0; k < k0 + 64; k++)
                acc = fmaf(h1s[k], W2[k * 100 + 25 * b + oo], acc);
        }
        part[tid] = acc;
    }
    __syncthreads();
    if (tid < 25) {
        float s = b2[25 * b + tid];
        #pragma unroll
        for (int c = 0; c < 8; c++) s += part[c * 32 + tid];   // fixed order
        g_proto[25 * b + tid] = leaky(s);
    }

    // ticket: last block computes pn2 from the completed proto
    __threadfence();
    if (tid == 0) slast = (atomicAdd(&g_doneB, 1u) == gridDim.x - 1) ? 1u : 0u;
    __syncthreads();
    if (!slast) return;
    __threadfence();
    if (tid < SLATE) {
        float s = 0.0f;
        #pragma unroll
        for (int d = 0; d < DDIM; d++) {
            float v = __ldcg(&g_proto[tid * DDIM + d]);
            s = fmaf(v, v, s);
        }
        g_pn2[tid] = s;
    }
    if (tid == 0) g_doneB = 0;   // reset for graph replay
}

// -------- kernel 2: sample keys + coarse hist; LAST BLOCK refines thresholds --
__global__ __launch_bounds__(512) void sample_kernel(const float* __restrict__ docs,
                                                     int N, int S)
{
    __shared__ unsigned shist[SLATE * NBINS];   // 40 KB
    __shared__ __align__(16) float sp[100];
    __shared__ float    spn[SLATE];
    __shared__ unsigned swarp[32];
    __shared__ unsigned sres, spre, slast;
    int tid = threadIdx.x;

    for (int t = tid; t < SLATE * NBINS; t += 512) shist[t] = 0;
    if (tid < 100) sp[tid] = g_proto[tid];
    if (tid < SLATE) spn[tid] = g_pn2[tid];
    __syncthreads();

    const float4* d4 = (const float4*)docs;
    for (int s = blockIdx.x * blockDim.x + tid; s < S; s += gridDim.x * blockDim.x) {
        int i = ((s >> 8) << 13) + (s & 255);   // chunk c -> docs [8192c, 8192c+256)
        if (i >= N) {
            #pragma unroll
            for (int j = 0; j < SLATE; j++)
                g_skey[(size_t)j * SMAX + s] = 0xFFFFFFFFu;   // sentinel
            continue;
        }
        float4 dv[5];
        size_t base = (size_t)i * 5;
        #pragma unroll
        for (int q = 0; q < 5; q++) dv[q] = d4[base + q];
        float vv[20];
        unpack20(dv, vv);
        float cn2 = norm20(vv);
        #pragma unroll
        for (int j = 0; j < SLATE; j++) {
            float dot = dot20v((const float4*)&sp[j * DDIM], vv);
            unsigned key = key20(cn2, dot, spn[j]);
            g_skey[(size_t)j * SMAX + s] = key;
            unsigned hidx = j * NBINS + (key >> 21);
            unsigned am = __activemask();
            unsigned m  = __match_any_sync(am, hidx);
            if ((int)(threadIdx.x & 31) == (__ffs(m) - 1))
                atomicAdd(&shist[hidx], (unsigned)__popc(m));
        }
    }
    __syncthreads();
    for (int t = tid; t < SLATE * NBINS; t += 512) {
        unsigned c = shist[t];
        if (c) atomicAdd(&g_hist[t], c);
    }

    // ---- last-block epilogue: per-row threshold refined to 2^10 keys ----
    __threadfence();
    if (tid == 0) slast = (atomicAdd(&g_done, 1u) == gridDim.x - 1) ? 1u : 0u;
    __syncthreads();
    if (!slast) return;
    __threadfence();

    for (int r = 0; r < SLATE; r++) {
        for (int i = tid; i < NBINS; i += 512)
            shist[i] = __ldcg(&g_hist[r * NBINS + i]);
        __syncthreads();
        find_bin<NBINS, 512>(shist, STGT, swarp, &sres, &spre);
        unsigned bA = sres, pfA = spre;
        __syncthreads();
        if (bA == 0xFFFFFFFFu) {
            if (tid == 0) g_thresh[r] = 0xFFFFFFFFu;
            __syncthreads();
            continue;
        }
        unsigned rB = STGT - pfA;
        for (int i = tid; i < NBINS; i += 512) shist[i] = 0;
        __syncthreads();
        for (int s = tid; s < S; s += 512) {
            unsigned k = __ldcg(&g_skey[(size_t)r * SMAX + s]);
            if ((k >> 21) == bA) atomicAdd(&shist[(k >> 10) & 0x7FFu], 1u);
        }
        __syncthreads();
        find_bin<NBINS, 512>(shist, rB, swarp, &sres, &spre);
        if (tid == 0) {
            unsigned long long T =
                ((((unsigned long long)bA << 11) | sres) + 1ull) << 10;
            g_thresh[r] = (T > 0xFFFFFFFFull) ? 0xFFFFFFFFu : (unsigned)T;
        }
        __syncthreads();
    }
    if (tid == 0) g_done = 0;   // reset for graph replay
}

// -------- kernel 3: fused score+collect, direct streaming LDG -------------
// 1 doc/thread grid-stride. __ldcs avoids L1 allocation on a one-pass stream.
// Fast path: single ballot on hitAny; per-j ballots only when a warp has hits.
// Per-j key comparisons are exact and bit-identical to the sample path.
__global__ __launch_bounds__(512) void score_kernel(const float* __restrict__ docs, int N)
{
    __shared__ __align__(16) float sp[100];
    __shared__ float    spn[SLATE];
    __shared__ unsigned sT[SLATE];
    int tid = threadIdx.x;

    if (tid < 100) sp[tid] = g_proto[tid];
    if (tid < SLATE) { spn[tid] = g_pn2[tid]; sT[tid] = g_thresh[tid]; }
    __syncthreads();

    const int lane = tid & 31;
    const float4* d4 = (const float4*)docs;
    int stride = gridDim.x * blockDim.x;

    for (int i = blockIdx.x * blockDim.x + tid; i < N; i += stride) {
        const float4* dp = d4 + (size_t)i * 5;
        float4 dv[5];
        #pragma unroll
        for (int q = 0; q < 5; q++) dv[q] = __ldcs(dp + q);
        float vv[20];
        unpack20(dv, vv);
        float cn2 = norm20(vv);

        unsigned keys[SLATE];
        unsigned hit = 0;
        #pragma unroll
        for (int j = 0; j < SLATE; j++) {
            float dot = dot20v((const float4*)&sp[j * DDIM], vv);
            keys[j] = key20(cn2, dot, spn[j]);
            hit |= (keys[j] < sT[j]) ? (1u << j) : 0u;
        }

        unsigned am = __activemask();
        if (__ballot_sync(am, hit != 0)) {      // rare slow path
            #pragma unroll
            for (int j = 0; j < SLATE; j++) {
                bool h = (hit >> j) & 1u;
                unsigned m = __ballot_sync(am, h);
                if (m) {
                    int ldr = __ffs(m) - 1;
                    unsigned bpos = 0;
                    if (lane == ldr)
                        bpos = atomicAdd(&g_candCount[j], (unsigned)__popc(m));
                    bpos = __shfl_sync(am, bpos, ldr);
                    if (h) {
                        unsigned pos = bpos + (unsigned)__popc(m & ((1u << lane) - 1u));
                        if (pos < CAP)
                            g_cand[(size_t)j * CAP + pos] =
                                ((unsigned long long)keys[j] << 32) | (unsigned)i;
                    }
                }
            }
        }
    }
}

// -------- kernel 4: radix select of exact 100th + rank survivors + gather ----
__global__ __launch_bounds__(1024) void select_kernel(
    const float* __restrict__ docs, float* __restrict__ out, int out_size)
{
    extern __shared__ unsigned long long sc[];
    __shared__ unsigned           hist[NBINS];
    __shared__ unsigned           swarp[32];
    __shared__ unsigned           sres, spre;
    __shared__ unsigned long long sv[SV_CAP];
    __shared__ unsigned           svCount;

    int j   = blockIdx.x;
    int tid = threadIdx.x;
    size_t cbase = (size_t)j * CAP;
    int n = (int)min(g_candCount[j], (unsigned)CAP);
    int nsh = n < SH_CAND ? n : SH_CAND;

    if (tid == 0) svCount = 0;
    for (int t = tid; t < nsh; t += 1024) sc[t] = g_cand[cbase + t];
    __syncthreads();

    // pass A: bits 31..21
    for (int i = tid; i < NBINS; i += 1024) hist[i] = 0;
    __syncthreads();
    for (int t = tid; t < n; t += 1024) {
        unsigned k = (unsigned)(((t < nsh) ? sc[t] : g_cand[cbase + t]) >> 32);
        unsigned b = k >> 21;
        unsigned am = __activemask();
        unsigned m  = __match_any_sync(am, b);
        if ((int)(tid & 31) == (__ffs(m) - 1)) atomicAdd(&hist[b], (unsigned)__popc(m));
    }
    __syncthreads();
    find_bin<NBINS, 1024>(hist, KSEL, swarp, &sres, &spre);
    unsigned bA = sres;
    unsigned rB = KSEL - spre;
    __syncthreads();

    // pass B: bits 20..10 within bA
    for (int i = tid; i < NBINS; i += 1024) hist[i] = 0;
    __syncthreads();
    for (int t = tid; t < n; t += 1024) {
        unsigned k = (unsigned)(((t < nsh) ? sc[t] : g_cand[cbase + t]) >> 32);
        if ((k >> 21) == bA) atomicAdd(&hist[(k >> 10) & 0x7FFu], 1u);
    }
    __syncthreads();
    find_bin<NBINS, 1024>(hist, rB, swarp, &sres, &spre);
    unsigned bB = sres;
    unsigned rC = rB - spre;
    unsigned hi21 = (bA << 11) | bB;
    __syncthreads();

    // pass C: bits 9..0 within (bA,bB)
    if (tid < 1024) hist[tid] = 0;
    __syncthreads();
    for (int t = tid; t < n; t += 1024) {
        unsigned k = (unsigned)(((t < nsh) ? sc[t] : g_cand[cbase + t]) >> 32);
        if ((k >> 10) == hi21) atomicAdd(&hist[k & 0x3FFu], 1u);
    }
    __syncthreads();
    find_bin<1024, 1024>(hist, rC, swarp, &sres, &spre);
    unsigned Kstar = (hi21 << 10) | sres;
    __syncthreads();

    // survivors: key <= Kstar (ties resolved by packed 64-bit rank)
    for (int t = tid; t < n; t += 1024) {
        unsigned long long pk = (t < nsh) ? sc[t] : g_cand[cbase + t];
        if ((unsigned)(pk >> 32) <= Kstar) {
            unsigned pos = atomicAdd(&svCount, 1u);
            if (pos < SV_CAP) sv[pos] = pk;
        }
    }
    __syncthreads();

    int S = (int)min(svCount, (unsigned)SV_CAP);
    for (int t = tid; t < S; t += 1024) {
        unsigned long long my = sv[t];
        int rank = 0;
        for (int s = 0; s < S; s++) rank += (sv[s] < my);
        if (rank < KSEL) {
            unsigned di = (unsigned)(my & 0xFFFFFFFFu);
            int orow = j * KSEL + rank;
            if (out_size >= SLATE * KSEL * DDIM) {
                const float4* s4 = (const float4*)(docs + (size_t)di * DDIM);
                float4* o4 = (float4*)(out + (size_t)orow * DDIM);
                #pragma unroll
                for (int q = 0; q < 5; q++) o4[q] = s4[q];
                if (out_size >= SLATE * KSEL * DDIM + SLATE * KSEL)
                    out[SLATE * KSEL * DDIM + orow] = (float)di;
            } else {
                out[orow] = (float)di;
            }
        }
    }
}

extern "C" void kernel_launch(void* const* d_in, const int* in_sizes, int n_in,
                              void* d_out, int out_size)
{
    const float* state = (const float*)d_in[0];
    const float* docs  = (const float*)d_in[1];
    const float* W0    = (const float*)d_in[2];
    const float* b0    = (const float*)d_in[3];
    const float* W1    = (const float*)d_in[4];
    const float* b1    = (const float*)d_in[5];
    const float* W2    = (const float*)d_in[6];
    const float* b2    = (const float*)d_in[7];
    float* out = (float*)d_out;

    int N = in_sizes[1] / DDIM;
    int S = N >> 5;               // 1/32 sample
    if (S < 1) S = N;
    if (S > SMAX) S = SMAX;

    static int inited = 0;
    if (!inited) {
        cudaFuncSetAttribute(select_kernel,
            cudaFuncAttributeMaxDynamicSharedMemorySize, SH_CAND * sizeof(unsigned long long));
        inited = 1;
    }

    int sblocks = (N + 512 * 2 - 1) / (512 * 2);
    if (sblocks > 1184) sblocks = 1184;      // 8 blocks/SM
    if (sblocks < 1) sblocks = 1;

    mlpA_kernel<<<8, 256>>>(state, W0, b0, W1, b1);
    mlpB_kernel<<<4, 256>>>(W2, b2);
    sample_kernel<<<128, 512>>>(docs, N, S);
    score_kernel<<<sblocks, 512>>>(docs, N);
    select_kernel<<<SLATE, 1024, SH_CAND * sizeof(unsigned long long)>>>(docs, out, out_size);
}

// round 10
// speedup vs baseline: 2.2704x; 1.9480x over previous
#include <cuda_runtime.h>
#include <cstdint>

#define SLATE   5
#define DDIM    20
#define KSEL    100
#define NBINS   2048
#define CAP     131072
#define SMAX    131072
#define SH_CAND 12288
#define SV_CAP  512
#define STGT    128        // sample-count guarantee target (>= KSEL)

// -------- device scratch (allocation-free module globals) --------
__device__ float              g_proto[128];
__device__ float              g_pn2[8];
__device__ unsigned           g_hist[SLATE * NBINS];
__device__ unsigned           g_skey[(size_t)SLATE * SMAX];   // sample keys
__device__ unsigned           g_thresh[8];                    // exclusive key limit
__device__ unsigned           g_candCount[8];
__device__ unsigned long long g_cand[(size_t)SLATE * CAP];

__device__ __forceinline__ float leaky(float x) { return x > 0.0f ? x : 0.01f * x; }

// ---- scalar math: sample AND score use identical sequences (bit-identical keys)
__device__ __forceinline__ void unpack20(const float4* d5, float* vv) {
    #pragma unroll
    for (int q = 0; q < 5; q++) {
        float4 v = d5[q];
        vv[4*q+0] = v.x; vv[4*q+1] = v.y; vv[4*q+2] = v.z; vv[4*q+3] = v.w;
    }
}
__device__ __forceinline__ float norm20(const float* vv) {
    float c = 0.0f;
    #pragma unroll
    for (int k = 0; k < DDIM; k++) c = fmaf(vv[k], vv[k], c);
    return c;
}
__device__ __forceinline__ float dot20v(const float4* p, const float* vv) {
    float d = 0.0f;
    #pragma unroll
    for (int q = 0; q < 5; q++) {
        float4 w = p[q];
        d = fmaf(w.x, vv[4*q+0], d); d = fmaf(w.y, vv[4*q+1], d);
        d = fmaf(w.z, vv[4*q+2], d); d = fmaf(w.w, vv[4*q+3], d);
    }
    return d;
}
__device__ __forceinline__ unsigned key20(float cn2, float dot, float pn) {
    float d2 = fmaf(-2.0f, dot, cn2) + pn;
    d2 = fmaxf(d2, 0.0f);               // positive floats: raw bits monotone
    return __float_as_uint(d2);
}

// ---- block-wide "first bin with inclusive cum >= r" over NB bins ----
template<int NB, int BD>
__device__ void find_bin(const unsigned* hist, unsigned r, unsigned* warpsum,
                         unsigned* s_res, unsigned* s_prefix)
{
    const int tid = threadIdx.x;
    constexpr int PB = NB / BD;
    unsigned local[PB];
    unsigned v = 0;
    #pragma unroll
    for (int p = 0; p < PB; p++) { local[p] = hist[tid * PB + p]; v += local[p]; }

    unsigned inc = v;
    #pragma unroll
    for (int d = 1; d < 32; d <<= 1) {
        unsigned t = __shfl_up_sync(0xFFFFFFFFu, inc, d);
        if ((tid & 31) >= d) inc += t;
    }
    if ((tid & 31) == 31) warpsum[tid >> 5] = inc;
    if (tid == 0) *s_res = 0xFFFFFFFFu;
    __syncthreads();

    if (tid < 32) {
        constexpr int NW = BD / 32;
        unsigned w = (tid < NW) ? warpsum[tid] : 0u;
        #pragma unroll
        for (int d = 1; d < 32; d <<= 1) {
            unsigned t = __shfl_up_sync(0xFFFFFFFFu, w, d);
            if (tid >= d) w += t;
        }
        warpsum[tid] = w;
    }
    __syncthreads();

    unsigned base   = (tid >= 32) ? warpsum[(tid >> 5) - 1] : 0u;
    unsigned before = base + inc - v;
    unsigned run = before;
    unsigned myBin = 0xFFFFFFFFu;
    #pragma unroll
    for (int p = 0; p < PB; p++) {
        run += local[p];
        if (myBin == 0xFFFFFFFFu && run >= r) myBin = (unsigned)(tid * PB + p);
    }
    if (myBin != 0xFFFFFFFFu) atomicMin(s_res, myBin);
    __syncthreads();

    unsigned winner = *s_res;
    if (winner != 0xFFFFFFFFu && winner / PB == (unsigned)tid) {
        unsigned pf = before;
        for (unsigned p = 0; p < winner % PB; p++) pf += local[p];
        *s_prefix = pf;
    }
    __syncthreads();
}

// -------- kernel 1: MLP (o-vectorized float4 GEMVs) + zero scratch --------
__global__ __launch_bounds__(1024) void mlp_kernel(
    const float* __restrict__ x_in,
    const float* __restrict__ W0, const float* __restrict__ b0,
    const float* __restrict__ W1, const float* __restrict__ b1,
    const float* __restrict__ W2, const float* __restrict__ b2)
{
    __shared__ float x[DDIM];
    __shared__ float h0[256];
    __shared__ float h1[512];
    __shared__ float p2[8 * 512];
    __shared__ float p3[32 * 100];
    __shared__ float pr[100];
    int tid = threadIdx.x;

    for (int i = tid; i < SLATE * NBINS; i += 1024) g_hist[i] = 0;
    if (tid < 8) g_candCount[tid] = 0;

    if (tid < DDIM) x[tid] = x_in[tid];
    __syncthreads();

    if (tid < 256) {
        float acc = b0[tid];
        #pragma unroll
        for (int k = 0; k < DDIM; k++) acc = fmaf(x[k], W0[k * 256 + tid], acc);
        h0[tid] = leaky(acc);
    }
    __syncthreads();

    {   // layer 2: 512 outputs; float4 along o, k split 8 ways
        int o4 = (tid & 127);
        int c  = tid >> 7;
        const float4* W1v = (const float4*)W1;
        float4 acc = make_float4(0.f, 0.f, 0.f, 0.f);
        int k0 = c * 32;
        #pragma unroll 8
        for (int k = k0; k < k0 + 32; k++) {
            float h = h0[k];
            float4 w = W1v[k * 128 + o4];
            acc.x = fmaf(h, w.x, acc.x); acc.y = fmaf(h, w.y, acc.y);
            acc.z = fmaf(h, w.z, acc.z); acc.w = fmaf(h, w.w, acc.w);
        }
        ((float4*)(p2 + c * 512))[o4] = acc;
    }
    __syncthreads();
    if (tid < 512) {
        float s = b1[tid];
        #pragma unroll
        for (int c = 0; c < 8; c++) s += p2[c * 512 + tid];
        h1[tid] = leaky(s);
    }
    __syncthreads();

    {   // layer 3: 100 outputs; float4 along o, k split 32 ways
        int t = tid & 31;
        int c = tid >> 5;
        if (t < 25) {
            const float4* W2v = (const float4*)W2;
            float4 acc = make_float4(0.f, 0.f, 0.f, 0.f);
            int k0 = c * 16;
            #pragma unroll 8
            for (int k = k0; k < k0 + 16; k++) {
                float h = h1[k];
                float4 w = W2v[k * 25 + t];
                acc.x = fmaf(h, w.x, acc.x); acc.y = fmaf(h, w.y, acc.y);
                acc.z = fmaf(h, w.z, acc.z); acc.w = fmaf(h, w.w, acc.w);
            }
            p3[c * 100 + 4 * t + 0] = acc.x;
            p3[c * 100 + 4 * t + 1] = acc.y;
            p3[c * 100 + 4 * t + 2] = acc.z;
            p3[c * 100 + 4 * t + 3] = acc.w;
        }
    }
    __syncthreads();
    if (tid < 100) {
        float s = b2[tid];
        #pragma unroll
        for (int c = 0; c < 32; c++) s += p3[c * 100 + tid];
        float v = leaky(s);
        pr[tid] = v;
        g_proto[tid] = v;
    }
    __syncthreads();
    if (tid < SLATE) {
        float s = 0.0f;
        #pragma unroll
        for (int d = 0; d < DDIM; d++) { float v = pr[tid * DDIM + d]; s = fmaf(v, v, s); }
        g_pn2[tid] = s;
    }
}

// -------- kernel 2: sample keys + coarse histogram (1/32 of docs) --------
__global__ __launch_bounds__(512) void sample_kernel(const float* __restrict__ docs,
                                                     int N, int S)
{
    __shared__ unsigned shist[SLATE * NBINS];
    __shared__ __align__(16) float sp[100];
    __shared__ float    spn[SLATE];
    int tid = threadIdx.x;

    for (int t = tid; t < SLATE * NBINS; t += 512) shist[t] = 0;
    if (tid < 100) sp[tid] = g_proto[tid];
    if (tid < SLATE) spn[tid] = g_pn2[tid];
    __syncthreads();

    const float4* d4 = (const float4*)docs;
    for (int s = blockIdx.x * blockDim.x + tid; s < S; s += gridDim.x * blockDim.x) {
        int i = ((s >> 8) << 13) + (s & 255);   // chunk c -> docs [8192c, 8192c+256)
        if (i >= N) {
            #pragma unroll
            for (int j = 0; j < SLATE; j++)
                g_skey[(size_t)j * SMAX + s] = 0xFFFFFFFFu;   // sentinel
            continue;
        }
        float4 dv[5];
        size_t base = (size_t)i * 5;
        #pragma unroll
        for (int q = 0; q < 5; q++) dv[q] = d4[base + q];
        float vv[20];
        unpack20(dv, vv);
        float cn2 = norm20(vv);
        #pragma unroll
        for (int j = 0; j < SLATE; j++) {
            float dot = dot20v((const float4*)&sp[j * DDIM], vv);
            unsigned key = key20(cn2, dot, spn[j]);
            g_skey[(size_t)j * SMAX + s] = key;
            unsigned hidx = j * NBINS + (key >> 21);
            unsigned am = __activemask();
            unsigned m  = __match_any_sync(am, hidx);
            if ((int)(threadIdx.x & 31) == (__ffs(m) - 1))
                atomicAdd(&shist[hidx], (unsigned)__popc(m));
        }
    }
    __syncthreads();
    for (int t = tid; t < SLATE * NBINS; t += 512) {
        unsigned c = shist[t];
        if (c) atomicAdd(&g_hist[t], c);
    }
}

// -------- kernel 3: refine threshold to 2^10 key granularity --------
__global__ __launch_bounds__(1024) void refine_kernel(int S)
{
    __shared__ unsigned hist[NBINS];
    __shared__ unsigned swarp[32];
    __shared__ unsigned sres, spre;
    int j = blockIdx.x, tid = threadIdx.x;

    for (int i = tid; i < NBINS; i += 1024) hist[i] = g_hist[j * NBINS + i];
    __syncthreads();
    find_bin<NBINS, 1024>(hist, STGT, swarp, &sres, &spre);
    unsigned bA = sres, pfA = spre;
    __syncthreads();
    if (bA == 0xFFFFFFFFu) { if (tid == 0) g_thresh[j] = 0xFFFFFFFFu; return; }
    unsigned rB = STGT - pfA;

    for (int i = tid; i < NBINS; i += 1024) hist[i] = 0;
    __syncthreads();
    for (int s = tid; s < S; s += 1024) {
        unsigned k = g_skey[(size_t)j * SMAX + s];
        if ((k >> 21) == bA) atomicAdd(&hist[(k >> 10) & 0x7FFu], 1u);
    }
    __syncthreads();
    find_bin<NBINS, 1024>(hist, rB, swarp, &sres, &spre);
    if (tid == 0) {
        unsigned long long T =
            ((((unsigned long long)bA << 11) | sres) + 1ull) << 10;
        g_thresh[j] = (T > 0xFFFFFFFFull) ? 0xFFFFFFFFu : (unsigned)T;
    }
}

// -------- kernel 4: fused score+collect, direct streaming LDG -------------
// 1 doc/thread grid-stride. __ldcs avoids L1 allocation on a one-pass stream.
// Fast path: single ballot on hitAny; per-j ballots only when a warp has hits.
// Per-j key comparisons are exact and bit-identical to the sample path.
__global__ __launch_bounds__(512) void score_kernel(const float* __restrict__ docs, int N)
{
    __shared__ __align__(16) float sp[100];
    __shared__ float    spn[SLATE];
    __shared__ unsigned sT[SLATE];
    int tid = threadIdx.x;

    if (tid < 100) sp[tid] = g_proto[tid];
    if (tid < SLATE) { spn[tid] = g_pn2[tid]; sT[tid] = g_thresh[tid]; }
    __syncthreads();

    const int lane = tid & 31;
    const float4* d4 = (const float4*)docs;
    int stride = gridDim.x * blockDim.x;

    for (int i = blockIdx.x * blockDim.x + tid; i < N; i += stride) {
        const float4* dp = d4 + (size_t)i * 5;
        float4 dv[5];
        #pragma unroll
        for (int q = 0; q < 5; q++) dv[q] = __ldcs(dp + q);
        float vv[20];
        unpack20(dv, vv);
        float cn2 = norm20(vv);

        unsigned keys[SLATE];
        unsigned hit = 0;
        #pragma unroll
        for (int j = 0; j < SLATE; j++) {
            float dot = dot20v((const float4*)&sp[j * DDIM], vv);
            keys[j] = key20(cn2, dot, spn[j]);
            hit |= (keys[j] < sT[j]) ? (1u << j) : 0u;
        }

        unsigned am = __activemask();
        if (__ballot_sync(am, hit != 0)) {      // rare slow path
            #pragma unroll
            for (int j = 0; j < SLATE; j++) {
                bool h = (hit >> j) & 1u;
                unsigned m = __ballot_sync(am, h);
                if (m) {
                    int ldr = __ffs(m) - 1;
                    unsigned bpos = 0;
                    if (lane == ldr)
                        bpos = atomicAdd(&g_candCount[j], (unsigned)__popc(m));
                    bpos = __shfl_sync(am, bpos, ldr);
                    if (h) {
                        unsigned pos = bpos + (unsigned)__popc(m & ((1u << lane) - 1u));
                        if (pos < CAP)
                            g_cand[(size_t)j * CAP + pos] =
                                ((unsigned long long)keys[j] << 32) | (unsigned)i;
                    }
                }
            }
        }
    }
}

// -------- kernel 5: radix select of exact 100th + rank survivors + gather ----
__global__ __launch_bounds__(1024) void select_kernel(
    const float* __restrict__ docs, float* __restrict__ out, int out_size)
{
    extern __shared__ unsigned long long sc[];
    __shared__ unsigned           hist[NBINS];
    __shared__ unsigned           swarp[32];
    __shared__ unsigned           sres, spre;
    __shared__ unsigned long long sv[SV_CAP];
    __shared__ unsigned           svCount;

    int j   = blockIdx.x;
    int tid = threadIdx.x;
    size_t cbase = (size_t)j * CAP;
    int n = (int)min(g_candCount[j], (unsigned)CAP);
    int nsh = n < SH_CAND ? n : SH_CAND;

    if (tid == 0) svCount = 0;
    for (int t = tid; t < nsh; t += 1024) sc[t] = g_cand[cbase + t];
    __syncthreads();

    // pass A: bits 31..21
    for (int i = tid; i < NBINS; i += 1024) hist[i] = 0;
    __syncthreads();
    for (int t = tid; t < n; t += 1024) {
        unsigned k = (unsigned)(((t < nsh) ? sc[t] : g_cand[cbase + t]) >> 32);
        unsigned b = k >> 21;
        unsigned am = __activemask();
        unsigned m  = __match_any_sync(am, b);
        if ((int)(tid & 31) == (__ffs(m) - 1)) atomicAdd(&hist[b], (unsigned)__popc(m));
    }
    __syncthreads();
    find_bin<NBINS, 1024>(hist, KSEL, swarp, &sres, &spre);
    unsigned bA = sres;
    unsigned rB = KSEL - spre;
    __syncthreads();

    // pass B: bits 20..10 within bA
    for (int i = tid; i < NBINS; i += 1024) hist[i] = 0;
    __syncthreads();
    for (int t = tid; t < n; t += 1024) {
        unsigned k = (unsigned)(((t < nsh) ? sc[t] : g_cand[cbase + t]) >> 32);
        if ((k >> 21) == bA) atomicAdd(&hist[(k >> 10) & 0x7FFu], 1u);
    }
    __syncthreads();
    find_bin<NBINS, 1024>(hist, rB, swarp, &sres, &spre);
    unsigned bB = sres;
    unsigned rC = rB - spre;
    unsigned hi21 = (bA << 11) | bB;
    __syncthreads();

    // pass C: bits 9..0 within (bA,bB)
    if (tid < 1024) hist[tid] = 0;
    __syncthreads();
    for (int t = tid; t < n; t += 1024) {
        unsigned k = (unsigned)(((t < nsh) ? sc[t] : g_cand[cbase + t]) >> 32);
        if ((k >> 10) == hi21) atomicAdd(&hist[k & 0x3FFu], 1u);
    }
    __syncthreads();
    find_bin<1024, 1024>(hist, rC, swarp, &sres, &spre);
    unsigned Kstar = (hi21 << 10) | sres;
    __syncthreads();

    // survivors: key <= Kstar (ties resolved by packed 64-bit rank)
    for (int t = tid; t < n; t += 1024) {
        unsigned long long pk = (t < nsh) ? sc[t] : g_cand[cbase + t];
        if ((unsigned)(pk >> 32) <= Kstar) {
            unsigned pos = atomicAdd(&svCount, 1u);
            if (pos < SV_CAP) sv[pos] = pk;
        }
    }
    __syncthreads();

    int S = (int)min(svCount, (unsigned)SV_CAP);
    for (int t = tid; t < S; t += 1024) {
        unsigned long long my = sv[t];
        int rank = 0;
        for (int s = 0; s < S; s++) rank += (sv[s] < my);
        if (rank < KSEL) {
            unsigned di = (unsigned)(my & 0xFFFFFFFFu);
            int orow = j * KSEL + rank;
            if (out_size >= SLATE * KSEL * DDIM) {
                const float4* s4 = (const float4*)(docs + (size_t)di * DDIM);
                float4* o4 = (float4*)(out + (size_t)orow * DDIM);
                #pragma unroll
                for (int q = 0; q < 5; q++) o4[q] = s4[q];
                if (out_size >= SLATE * KSEL * DDIM + SLATE * KSEL)
                    out[SLATE * KSEL * DDIM + orow] = (float)di;
            } else {
                out[orow] = (float)di;
            }
        }
    }
}

extern "C" void kernel_launch(void* const* d_in, const int* in_sizes, int n_in,
                              void* d_out, int out_size)
{
    const float* state = (const float*)d_in[0];
    const float* docs  = (const float*)d_in[1];
    const float* W0    = (const float*)d_in[2];
    const float* b0    = (const float*)d_in[3];
    const float* W1    = (const float*)d_in[4];
    const float* b1    = (const float*)d_in[5];
    const float* W2    = (const float*)d_in[6];
    const float* b2    = (const float*)d_in[7];
    float* out = (float*)d_out;

    int N = in_sizes[1] / DDIM;
    int S = N >> 5;               // 1/32 sample
    if (S < 1) S = N;
    if (S > SMAX) S = SMAX;

    static int inited = 0;
    if (!inited) {
        cudaFuncSetAttribute(select_kernel,
            cudaFuncAttributeMaxDynamicSharedMemorySize, SH_CAND * sizeof(unsigned long long));
        inited = 1;
    }

    int sblocks = (N + 512 * 2 - 1) / (512 * 2);
    if (sblocks > 1184) sblocks = 1184;      // 8 blocks/SM
    if (sblocks < 1) sblocks = 1;

    mlp_kernel<<<1, 1024>>>(state, W0, b0, W1, b1, W2, b2);
    sample_kernel<<<128, 512>>>(docs, N, S);
    refine_kernel<<<SLATE, 1024>>>(S);
    score_kernel<<<sblocks, 512>>>(docs, N);
    select_kernel<<<SLATE, 1024, SH_CAND * sizeof(unsigned long long)>>>(docs, out, out_size);
}